// round 2
// baseline (speedup 1.0000x reference)
#include <cuda_runtime.h>

#define NQb   14
#define NLAY  5
#define NACT  6
#define NST   16384
#define NTHR  512
#define NPASS 20

struct PassT {
    unsigned short v[4];   // physical flip mask per gate (column of L)
    unsigned short r[4];   // logical-value parity mask per gate (row of L^-1)
    unsigned char  pos[12];// deposit positions for group-enumeration bits
    int k;                 // qubits fused in this pass (4 or 2)
    int matBase;           // index into per-CTA matrix table (l*14+q0)
};
struct Tables {
    PassT pass[NPASS];
    unsigned short finalR[NACT];
};

// GF(2)-linear storage swizzle: preserves XOR-offset conflict structure.
__device__ __forceinline__ int phi(int e) {
    return e ^ ((e >> 5) & 31) ^ ((e >> 10) & 15);
}

template<int K>
__device__ __forceinline__ void do_pass(float2* __restrict__ st,
                                        const float4* __restrict__ mats,
                                        const PassT& P, int tid) {
    const int M  = 1 << K;
    const int NB = NQb - K;

    int offp[M];
    offp[0] = 0;
#pragma unroll
    for (int j = 0; j < K; j++) {
        int vp = phi((int)P.v[j]);
#pragma unroll
        for (int c = 0; c < (1 << j); c++) offp[c | (1 << j)] = offp[c] ^ vp;
    }
    float4 Mt[K];
#pragma unroll
    for (int j = 0; j < K; j++) Mt[j] = mats[P.matBase + j];
    int rmask[K];
#pragma unroll
    for (int j = 0; j < K; j++) rmask[j] = P.r[j];
    int pos[NB];
#pragma unroll
    for (int j = 0; j < NB; j++) pos[j] = P.pos[j];

    const int NG = NST >> K;
#pragma unroll 1
    for (int g = tid; g < NG; g += NTHR) {
        int rep = 0;
#pragma unroll
        for (int j = 0; j < NB; j++) rep |= ((g >> j) & 1) << pos[j];
        int base = phi(rep);

        float2 s[M];
#pragma unroll
        for (int c = 0; c < M; c++) s[c] = st[base ^ offp[c]];

#pragma unroll
        for (int j = 0; j < K; j++) {
            unsigned u = __popc(rep & rmask[j]) & 1u;
            // SU(2) gate [[a,b],[-conj(b),conj(a)]]; u=1 swaps logical roles,
            // equivalent to (a,b) -> (conj(a), -conj(b))
            float are = Mt[j].x;
            float aim = u ? -Mt[j].y : Mt[j].y;
            float bre = u ? -Mt[j].z : Mt[j].z;
            float bim = Mt[j].w;
#pragma unroll
            for (int c = 0; c < M; c++) {
                if (c & (1 << j)) continue;
                int c1 = c | (1 << j);
                float2 A = s[c], B = s[c1];
                float2 nA, nB;
                nA.x = are * A.x - aim * A.y + bre * B.x - bim * B.y;
                nA.y = are * A.y + aim * A.x + bre * B.y + bim * B.x;
                nB.x = -bre * A.x - bim * A.y + are * B.x + aim * B.y;
                nB.y = -bre * A.y + bim * A.x + are * B.y - aim * B.x;
                s[c]  = nA;
                s[c1] = nB;
            }
        }
#pragma unroll
        for (int c = 0; c < M; c++) st[base ^ offp[c]] = s[c];
    }
}

__global__ void __launch_bounds__(NTHR, 1)
qsim_kernel(const float* __restrict__ x, const float* __restrict__ iscal,
            const float* __restrict__ wts, const float* __restrict__ ascale,
            const float* __restrict__ abias, float* __restrict__ out, Tables T)
{
    extern __shared__ char smem[];
    float2* st   = (float2*)smem;
    float4* mats = (float4*)(smem + NST * 8);
    float*  red  = (float*)(smem + NST * 8 + NLAY * NQb * 16);

    int b = blockIdx.x, tid = threadIdx.x;

    // Per-(layer,qubit) fused SU(2) matrix: U = RY(beta) RZ(gamma) RY(alpha)
    if (tid < NLAY * NQb) {
        int l = tid / NQb, q = tid % NQb;
        float xv    = x[b * NQb + q];
        float alpha = iscal[l * 2 * NQb + q] * xv;
        float gamma = iscal[l * 2 * NQb + NQb + q] * xv + wts[l * 2 * NQb + q];
        float beta  = wts[l * 2 * NQb + NQb + q];
        float sa, ca, sg, cg, sb, cb;
        sincosf(0.5f * alpha, &sa, &ca);
        sincosf(0.5f * gamma, &sg, &cg);
        sincosf(0.5f * beta,  &sb, &cb);
        float t0 = cb * ca - sb * sa;
        float t1 = cb * ca + sb * sa;
        float t2 = cb * sa + sb * ca;
        float t3 = cb * sa - sb * ca;
        float4 m;
        m.x =  cg * t0;   // Re(a)
        m.y = -sg * t1;   // Im(a)
        m.z = -cg * t2;   // Re(b)
        m.w =  sg * t3;   // Im(b)
        mats[tid] = m;
    }
    // |0...0>
    for (int e = tid; e < NST; e += NTHR) {
        float2 v; v.x = (e == 0) ? 1.f : 0.f; v.y = 0.f;
        st[phi(e)] = v;
    }
    __syncthreads();

#pragma unroll 1
    for (int p = 0; p < NPASS; p++) {
        if (T.pass[p].k == 4) do_pass<4>(st, mats, T.pass[p], tid);
        else                  do_pass<2>(st, mats, T.pass[p], tid);
        __syncthreads();
    }

    // <Z_i> for qubits 0..5 in the final frame
    float acc[NACT];
#pragma unroll
    for (int i = 0; i < NACT; i++) acc[i] = 0.f;
    int fr[NACT];
#pragma unroll
    for (int i = 0; i < NACT; i++) fr[i] = T.finalR[i];

#pragma unroll 1
    for (int j = 0; j < NST / NTHR; j++) {
        int e = (j * NTHR) | tid;
        float2 a = st[phi(e)];
        float pr = a.x * a.x + a.y * a.y;
#pragma unroll
        for (int i = 0; i < NACT; i++)
            acc[i] += (__popc(e & fr[i]) & 1) ? -pr : pr;
    }
#pragma unroll
    for (int o = 16; o > 0; o >>= 1)
#pragma unroll
        for (int i = 0; i < NACT; i++)
            acc[i] += __shfl_xor_sync(0xffffffffu, acc[i], o);

    int warp = tid >> 5, lane = tid & 31;
    if (lane == 0)
#pragma unroll
        for (int i = 0; i < NACT; i++) red[warp * NACT + i] = acc[i];
    __syncthreads();
    if (tid < NACT) {
        float s = 0.f;
        for (int w2 = 0; w2 < NTHR / 32; w2++) s += red[w2 * NACT + tid];
        out[b * NACT + tid] = s * ascale[tid] + abias[tid];
    }
}

// ---------------- host: frame tracking + pass tables ----------------

static void buildTables(Tables& T) {
    unsigned short Lc[NQb], Rr[NQb];
    for (int q = 0; q < NQb; q++) { Lc[q] = (unsigned short)(1u << (13 - q)); Rr[q] = Lc[q]; }
    static const int q0s[4] = {0, 4, 8, 12};
    static const int ks[4]  = {4, 4, 4, 2};

    for (int l = 0; l < NLAY; l++) {
        for (int gi = 0; gi < 4; gi++) {
            PassT& P = T.pass[l * 4 + gi];
            int k = ks[gi];
            P.k = k;
            P.matBase = l * NQb + q0s[gi];

            unsigned short red[4]; int piv[4];
            for (int j = 0; j < k; j++) {
                unsigned short wv = Lc[q0s[gi] + j];
                P.v[j] = wv;
                P.r[j] = Rr[q0s[gi] + j];
                for (int jj = 0; jj < j; jj++)
                    if ((wv >> piv[jj]) & 1) wv ^= red[jj];
                int p = 13; while (!((wv >> p) & 1)) p--;
                piv[j] = p; red[j] = wv;
            }
            for (int j = k; j < 4; j++) { P.v[j] = 0; P.r[j] = 0; }

            bool isp[14] = {false};
            for (int j = 0; j < k; j++) isp[piv[j]] = true;
            int npos[14], nn = 0;
            for (int p = 0; p < 14; p++) if (!isp[p]) npos[nn++] = p;

            // pick 5 lane bits with distinct bank residues under phi
            bool used[14] = {false};
            int lanep[5]; int nl = 0;
            for (int r = 0; r < 5; r++) {
                for (int ii = 0; ii < nn; ii++) {
                    if (used[ii]) continue;
                    int p  = npos[ii];
                    int rr = (p < 10) ? (p % 5) : (p - 10);
                    if (rr == r) { lanep[nl++] = p; used[ii] = true; break; }
                }
            }
            for (int ii = 0; ii < nn && nl < 5; ii++)
                if (!used[ii]) { lanep[nl++] = npos[ii]; used[ii] = true; }

            int idx = 0;
            for (int j = 0; j < 5; j++) P.pos[idx++] = (unsigned char)lanep[j];
            for (int ii = 0; ii < nn; ii++)
                if (!used[ii]) P.pos[idx++] = (unsigned char)npos[ii];
            while (idx < 12) P.pos[idx++] = 0;
        }
        // CNOT ring ladder -> frame update only
        for (int i = 0; i < NQb; i++) {
            int c = i, t = (i + 1) % NQb;
            Lc[c] ^= Lc[t];
            Rr[t] ^= Rr[c];
        }
    }
    for (int i = 0; i < NACT; i++) T.finalR[i] = Rr[i];
}

extern "C" void kernel_launch(void* const* d_in, const int* in_sizes, int n_in,
                              void* d_out, int out_size) {
    const float* x      = (const float*)d_in[0];
    const float* iscal  = (const float*)d_in[1];
    const float* wts    = (const float*)d_in[2];
    const float* ascale = (const float*)d_in[3];
    const float* abias  = (const float*)d_in[4];
    float* out = (float*)d_out;
    int B = out_size / NACT;

    Tables T;
    buildTables(T);

    size_t smem = (size_t)NST * 8 + NLAY * NQb * 16 + (NTHR / 32) * NACT * 4;
    cudaFuncSetAttribute(qsim_kernel, cudaFuncAttributeMaxDynamicSharedMemorySize, (int)smem);
    qsim_kernel<<<B, NTHR, smem>>>(x, iscal, wts, ascale, abias, out, T);
}

// round 3
// speedup vs baseline: 1.3333x; 1.3333x over previous
#include <cuda_runtime.h>

#define NQb   14
#define NLAY  5
#define NACT  6
#define NST   16384
#define NTHR  512
#define NPASS 20

struct PassT {
    unsigned short v[4];
    unsigned short r[4];
    unsigned char  pos[12];
    int k;
    int matBase;
};
struct Tables {
    PassT pass[NPASS];
    unsigned short finalR[NACT];
};

typedef unsigned long long ull;

// GF(2)-linear storage swizzle.
__device__ __forceinline__ int phi(int e) {
    return e ^ ((e >> 5) & 31) ^ ((e >> 10) & 15);
}

__device__ __forceinline__ ull ffma2(ull a, ull b, ull c) {
    ull d;
    asm("fma.rn.f32x2 %0, %1, %2, %3;" : "=l"(d) : "l"(a), "l"(b), "l"(c));
    return d;
}
__device__ __forceinline__ ull fmul2(ull a, ull b) {
    ull d;
    asm("mul.rn.f32x2 %0, %1, %2;" : "=l"(d) : "l"(a), "l"(b));
    return d;
}
__device__ __forceinline__ ull pack2(float lo, float hi) {
    ull d;
    asm("mov.b64 %0, {%1, %2};" : "=l"(d) : "f"(lo), "f"(hi));
    return d;
}
__device__ __forceinline__ float ldf(const float* base, int byteoff) {
    return *(const float*)((const char*)base + byteoff);
}
__device__ __forceinline__ void stf(float* base, int byteoff, float v) {
    *(float*)((char*)base + byteoff) = v;
}

template<int K, int NB>
__device__ __forceinline__ void do_pass(float* __restrict__ st_re,
                                        float* __restrict__ st_im,
                                        const float4* __restrict__ mats,
                                        const PassT& P, int tid) {
    const int M = 1 << K;

    // byte-scaled swizzled cell offsets
    int offB[M];
    offB[0] = 0;
#pragma unroll
    for (int j = 0; j < K; j++) {
        int vp = phi((int)P.v[j]) * 4;
#pragma unroll
        for (int c = 0; c < (1 << j); c++) offB[c | (1 << j)] = offB[c] ^ vp;
    }
    float4 Mt[K];
#pragma unroll
    for (int j = 0; j < K; j++) Mt[j] = mats[P.matBase + j];
    int rmask[K];
#pragma unroll
    for (int j = 0; j < K; j++) rmask[j] = P.r[j];
    int pos[NB];
#pragma unroll
    for (int j = 0; j < NB; j++) pos[j] = P.pos[j];

    const int pairbit = 1 << pos[9];            // logical mask of pair-partner
    const int dB = phi(pairbit) * 4;            // its swizzled byte delta
    const int TITER = 1 << (NB - 10);

#pragma unroll 1
    for (int t = 0; t < TITER; t++) {
        int c0 = tid | (t << 10);               // counter, bit 9 == 0
        int rep0 = 0;
#pragma unroll
        for (int j = 0; j < NB; j++) rep0 |= ((c0 >> j) & 1) << pos[j];
        int rep1 = rep0 ^ pairbit;
        int b0 = phi(rep0) * 4;

        ull sre[M], sim[M];
#pragma unroll
        for (int c = 0; c < M; c++) {
            int a0 = b0 ^ offB[c];
            sre[c] = pack2(ldf(st_re, a0), ldf(st_re, a0 ^ dB));
            sim[c] = pack2(ldf(st_im, a0), ldf(st_im, a0 ^ dB));
        }

#pragma unroll
        for (int j = 0; j < K; j++) {
            unsigned u0 = __popc(rep0 & rmask[j]) & 1u;
            unsigned u1 = __popc(rep1 & rmask[j]) & 1u;
            float are = Mt[j].x, aim = Mt[j].y, bre = Mt[j].z, bim = Mt[j].w;
            float aim0 = u0 ? -aim : aim, aim1 = u1 ? -aim : aim;
            float bre0 = u0 ? -bre : bre, bre1 = u1 ? -bre : bre;
            ull pare = pack2(are, are);
            ull paim = pack2(aim0, aim1);
            ull naim = pack2(-aim0, -aim1);
            ull pbre = pack2(bre0, bre1);
            ull nbre = pack2(-bre0, -bre1);
            ull pbim = pack2(bim, bim);
            ull nbim = pack2(-bim, -bim);
#pragma unroll
            for (int c = 0; c < M; c++) {
                if (c & (1 << j)) continue;
                int c1 = c | (1 << j);
                ull Are = sre[c],  Aim = sim[c];
                ull Bre = sre[c1], Bim = sim[c1];
                // nA = a*A + b*B ; nB = -conj(b)*A + conj(a)*B (u folded)
                ull nAre = ffma2(pare, Are, ffma2(naim, Aim, ffma2(pbre, Bre, fmul2(nbim, Bim))));
                ull nAim = ffma2(pare, Aim, ffma2(paim, Are, ffma2(pbre, Bim, fmul2(pbim, Bre))));
                ull nBre = ffma2(nbre, Are, ffma2(nbim, Aim, ffma2(pare, Bre, fmul2(paim, Bim))));
                ull nBim = ffma2(nbre, Aim, ffma2(pbim, Are, ffma2(pare, Bim, fmul2(naim, Bre))));
                sre[c] = nAre; sim[c] = nAim;
                sre[c1] = nBre; sim[c1] = nBim;
            }
        }

#pragma unroll
        for (int c = 0; c < M; c++) {
            int a0 = b0 ^ offB[c];
            float lo, hi;
            asm("mov.b64 {%0, %1}, %2;" : "=f"(lo), "=f"(hi) : "l"(sre[c]));
            stf(st_re, a0, lo); stf(st_re, a0 ^ dB, hi);
            asm("mov.b64 {%0, %1}, %2;" : "=f"(lo), "=f"(hi) : "l"(sim[c]));
            stf(st_im, a0, lo); stf(st_im, a0 ^ dB, hi);
        }
    }
}

__global__ void __launch_bounds__(NTHR, 1)
qsim_kernel(const float* __restrict__ x, const float* __restrict__ iscal,
            const float* __restrict__ wts, const float* __restrict__ ascale,
            const float* __restrict__ abias, float* __restrict__ out, Tables T)
{
    extern __shared__ char smem[];
    float*  st_re = (float*)smem;
    float*  st_im = (float*)(smem + NST * 4);
    float4* mats  = (float4*)(smem + NST * 8);
    float*  red   = (float*)(smem + NST * 8 + NLAY * NQb * 16);

    int b = blockIdx.x, tid = threadIdx.x;

    // Fused per-(layer,qubit) SU(2): U = RY(beta) RZ(gamma) RY(alpha)
    if (tid < NLAY * NQb) {
        int l = tid / NQb, q = tid % NQb;
        float xv    = x[b * NQb + q];
        float alpha = iscal[l * 2 * NQb + q] * xv;
        float gamma = iscal[l * 2 * NQb + NQb + q] * xv + wts[l * 2 * NQb + q];
        float beta  = wts[l * 2 * NQb + NQb + q];
        float sa, ca, sg, cg, sb, cb;
        sincosf(0.5f * alpha, &sa, &ca);
        sincosf(0.5f * gamma, &sg, &cg);
        sincosf(0.5f * beta,  &sb, &cb);
        float t0 = cb * ca - sb * sa;
        float t1 = cb * ca + sb * sa;
        float t2 = cb * sa + sb * ca;
        float t3 = cb * sa - sb * ca;
        float4 m;
        m.x =  cg * t0;
        m.y = -sg * t1;
        m.z = -cg * t2;
        m.w =  sg * t3;
        mats[tid] = m;
    }
    for (int e = tid; e < NST; e += NTHR) {
        int s = phi(e);
        st_re[s] = (e == 0) ? 1.f : 0.f;
        st_im[s] = 0.f;
    }
    __syncthreads();

#pragma unroll 1
    for (int p = 0; p < NPASS; p++) {
        if (T.pass[p].k == 4) do_pass<4, 10>(st_re, st_im, mats, T.pass[p], tid);
        else                  do_pass<2, 12>(st_re, st_im, mats, T.pass[p], tid);
        __syncthreads();
    }

    float acc[NACT];
#pragma unroll
    for (int i = 0; i < NACT; i++) acc[i] = 0.f;
    int fr[NACT];
#pragma unroll
    for (int i = 0; i < NACT; i++) fr[i] = T.finalR[i];

#pragma unroll 1
    for (int j = 0; j < NST / NTHR; j++) {
        int e = (j * NTHR) | tid;
        int s = phi(e);
        float re = st_re[s], im = st_im[s];
        float pr = re * re + im * im;
#pragma unroll
        for (int i = 0; i < NACT; i++)
            acc[i] += (__popc(e & fr[i]) & 1) ? -pr : pr;
    }
#pragma unroll
    for (int o = 16; o > 0; o >>= 1)
#pragma unroll
        for (int i = 0; i < NACT; i++)
            acc[i] += __shfl_xor_sync(0xffffffffu, acc[i], o);

    int warp = tid >> 5, lane = tid & 31;
    if (lane == 0)
#pragma unroll
        for (int i = 0; i < NACT; i++) red[warp * NACT + i] = acc[i];
    __syncthreads();
    if (tid < NACT) {
        float s = 0.f;
        for (int w2 = 0; w2 < NTHR / 32; w2++) s += red[w2 * NACT + tid];
        out[b * NACT + tid] = s * ascale[tid] + abias[tid];
    }
}

// ---------------- host: frame tracking + pass tables ----------------

static void buildTables(Tables& T) {
    unsigned short Lc[NQb], Rr[NQb];
    for (int q = 0; q < NQb; q++) { Lc[q] = (unsigned short)(1u << (13 - q)); Rr[q] = Lc[q]; }
    static const int q0s[4] = {0, 4, 8, 12};
    static const int ks[4]  = {4, 4, 4, 2};

    for (int l = 0; l < NLAY; l++) {
        for (int gi = 0; gi < 4; gi++) {
            PassT& P = T.pass[l * 4 + gi];
            int k = ks[gi];
            P.k = k;
            P.matBase = l * NQb + q0s[gi];

            unsigned short red[4]; int piv[4];
            for (int j = 0; j < k; j++) {
                unsigned short wv = Lc[q0s[gi] + j];
                P.v[j] = wv;
                P.r[j] = Rr[q0s[gi] + j];
                for (int jj = 0; jj < j; jj++)
                    if ((wv >> piv[jj]) & 1) wv ^= red[jj];
                int p = 13; while (!((wv >> p) & 1)) p--;
                piv[j] = p; red[j] = wv;
            }
            for (int j = k; j < 4; j++) { P.v[j] = 0; P.r[j] = 0; }

            bool isp[14] = {false};
            for (int j = 0; j < k; j++) isp[piv[j]] = true;
            int npos[14], nn = 0;
            for (int p = 0; p < 14; p++) if (!isp[p]) npos[nn++] = p;

            // 5 lane bits with distinct bank residues (p mod 5) under phi
            bool used[14] = {false};
            int lanep[5]; int nl = 0;
            for (int r = 0; r < 5; r++) {
                for (int ii = 0; ii < nn; ii++) {
                    if (used[ii]) continue;
                    int p  = npos[ii];
                    int rr = (p < 10) ? (p % 5) : (p - 10);
                    if (rr == r) { lanep[nl++] = p; used[ii] = true; break; }
                }
            }
            for (int ii = 0; ii < nn && nl < 5; ii++)
                if (!used[ii]) { lanep[nl++] = npos[ii]; used[ii] = true; }

            int idx = 0;
            for (int j = 0; j < 5; j++) P.pos[idx++] = (unsigned char)lanep[j];
            for (int ii = 0; ii < nn; ii++)
                if (!used[ii]) P.pos[idx++] = (unsigned char)npos[ii];
            while (idx < 12) P.pos[idx++] = 0;
        }
        for (int i = 0; i < NQb; i++) {
            int c = i, t = (i + 1) % NQb;
            Lc[c] ^= Lc[t];
            Rr[t] ^= Rr[c];
        }
    }
    for (int i = 0; i < NACT; i++) T.finalR[i] = Rr[i];
}

extern "C" void kernel_launch(void* const* d_in, const int* in_sizes, int n_in,
                              void* d_out, int out_size) {
    const float* x      = (const float*)d_in[0];
    const float* iscal  = (const float*)d_in[1];
    const float* wts    = (const float*)d_in[2];
    const float* ascale = (const float*)d_in[3];
    const float* abias  = (const float*)d_in[4];
    float* out = (float*)d_out;
    int B = out_size / NACT;

    Tables T;
    buildTables(T);

    size_t smem = (size_t)NST * 8 + NLAY * NQb * 16 + (NTHR / 32) * NACT * 4;
    cudaFuncSetAttribute(qsim_kernel, cudaFuncAttributeMaxDynamicSharedMemorySize, (int)smem);
    qsim_kernel<<<B, NTHR, smem>>>(x, iscal, wts, ascale, abias, out, T);
}